// round 4
// baseline (speedup 1.0000x reference)
#include <cuda_runtime.h>
#include <float.h>

// Problem constants (fixed by the reference: B=16, N=1024, M=21, D=256, V=16)
#define BN_TOTAL (16 * 1024)
#define MPTS 21
#define PP 20      // M-1 points per polyline
#define D1 128
#define D2 256

typedef unsigned long long ull;

// ---- packed f32x2 helpers (Blackwell FFMA2) ----
__device__ __forceinline__ ull pack2(float x, float y) {
    ull r;
    asm("mov.b64 %0, {%1, %2};" : "=l"(r) : "f"(x), "f"(y));
    return r;
}
__device__ __forceinline__ void unpack2(ull v, float& x, float& y) {
    asm("mov.b64 {%0, %1}, %2;" : "=f"(x), "=f"(y) : "l"(v));
}
__device__ __forceinline__ ull ffma2(ull a, ull b, ull c) {
    ull d;
    asm("fma.rn.f32x2 %0, %1, %2, %3;" : "=l"(d) : "l"(a), "l"(b), "l"(c));
    return d;
}

__device__ int g_mask_is_byte;

// Detect whether map_mask is stored as 1-byte bool or 4-byte int32.
__global__ void detect_mask_kernel(const unsigned char* __restrict__ m) {
    __shared__ int s_found;
    if (threadIdx.x == 0) s_found = 0;
    __syncthreads();
    int found = 0;
    for (int i = threadIdx.x; i < BN_TOTAL; i += blockDim.x) {
        if ((i & 3) != 0 && m[i] != 0) found = 1;
    }
    if (found) atomicOr(&s_found, 1);
    __syncthreads();
    if (threadIdx.x == 0) g_mask_is_byte = s_found;
}

// 64 threads/block. Thread t owns output columns 4t..4t+3 of every GEMM and
// ALL 20 points: per c-iter 1 LDG.128 + 5 LDS.128 feed 40 FFMA2.
__global__ __launch_bounds__(64) void map_encoder_kernel(
    const float* __restrict__ tgt,      // (B,N,21,2)
    const int* __restrict__ label,      // (B,N)
    const void* __restrict__ maskp,     // (B,N) bool or int32
    const float* __restrict__ W1, const float* __restrict__ b1,
    const float* __restrict__ g1, const float* __restrict__ be1,
    const float* __restrict__ m1, const float* __restrict__ v1,
    const float* __restrict__ W2, const float* __restrict__ b2,
    const float* __restrict__ W3, const float* __restrict__ b3,
    const float* __restrict__ g2, const float* __restrict__ be2,
    const float* __restrict__ m2, const float* __restrict__ v2,
    const float* __restrict__ W4, const float* __restrict__ b4,
    const float* __restrict__ temb,     // (16,256)
    const float* __restrict__ Wp1, const float* __restrict__ bp1,
    const float* __restrict__ Wp2, const float* __restrict__ bp2,
    const float* __restrict__ pcr,      // (6,)
    float* __restrict__ out)
{
    // [channel][point] transposed intermediates; 20-float (80B) rows are
    // 16B-aligned (80 = 5*16) -> 5x LDS.128 per row.
    __shared__ __align__(16) float sm_hT[D2 * PP];   // stage2 output h      (20 KB)
    __shared__ __align__(16) float sm_buf[D2 * PP];  // h1T->h2T->hp (reuse) (20 KB)
    __shared__ __align__(16) float sm_vec[D2];       // pooled -> sine
    __shared__ float sm_pts[MPTS * 2 + 2];
    __shared__ float sm_feat[PP * 6];

    const int idx = blockIdx.x;
    const int t = threadIdx.x;          // 0..63; owns cols 4t..4t+3

    bool mask;
    if (g_mask_is_byte)
        mask = ((const unsigned char*)maskp)[idx] != 0;
    else
        mask = ((const int*)maskp)[idx] != 0;

    float* __restrict__ feats_out = out;
    float* __restrict__ pos_out   = out + (size_t)BN_TOTAL * D2;
    float* __restrict__ mask_out  = out + (size_t)2 * BN_TOTAL * D2;

    if (!mask) {
        *(float4*)&feats_out[(size_t)idx * D2 + 4 * t] = make_float4(0.f, 0.f, 0.f, 0.f);
        *(float4*)&pos_out[(size_t)idx * D2 + 4 * t]   = make_float4(0.f, 0.f, 0.f, 0.f);
        if (t == 0) mask_out[idx] = 1.0f;
        return;
    }
    if (t == 0) mask_out[idx] = 0.0f;

    // ---- load points ----
    const float* pp = tgt + (size_t)idx * MPTS * 2;
    if (t < MPTS * 2) sm_pts[t] = pp[t];
    __syncthreads();

    // ---- feature construction ----
    if (t < PP) {
        int p = t;
        float cx = sm_pts[10 * 2], cy = sm_pts[10 * 2 + 1];
        float x0 = sm_pts[2 * p],     y0 = sm_pts[2 * p + 1];
        float x1 = sm_pts[2 * p + 2], y1 = sm_pts[2 * p + 3];
        float pvx = x1 - x0, pvy = y1 - y0;
        float vn = sqrtf(pvx * pvx + pvy * pvy) + 1.0f + 1e-6f;
        float inv = 1.0f / vn;
        sm_feat[p * 6 + 0] = x0 - cx;
        sm_feat[p * 6 + 1] = y0 - cy;
        sm_feat[p * 6 + 2] = pvx;
        sm_feat[p * 6 + 3] = pvy;
        sm_feat[p * 6 + 4] = pvx * inv;
        sm_feat[p * 6 + 5] = pvy * inv;
    }
    __syncthreads();

    // ---- stage 1: feat(20x6)@W1(6x128)+b1 -> BN1 -> relu -> sm_buf=h1T ----
    // thread t handles channels t and t+64
    #pragma unroll
    for (int half = 0; half < 2; ++half) {
        int d = t + half * 64;
        float w0 = W1[0 * D1 + d], w1 = W1[1 * D1 + d], w2 = W1[2 * D1 + d];
        float w3 = W1[3 * D1 + d], w4 = W1[4 * D1 + d], w5 = W1[5 * D1 + d];
        float s  = g1[d] * rsqrtf(v1[d] + 1e-5f);
        float sh = be1[d] - m1[d] * s + b1[d] * s;
        #pragma unroll
        for (int p = 0; p < PP; ++p) {
            const float* f = &sm_feat[p * 6];
            float lin = f[0] * w0 + f[1] * w1 + f[2] * w2
                      + f[3] * w3 + f[4] * w4 + f[5] * w5;
            sm_buf[d * PP + p] = fmaxf(lin * s + sh, 0.0f);
        }
    }
    __syncthreads();

    // ---- stage 2: h1(20x128)@W2(128x256)+b2 ; pooled = max_p (thread-local) ----
    {
        ull acc[4][10];
        #pragma unroll
        for (int j = 0; j < 4; ++j)
            #pragma unroll
            for (int q = 0; q < 10; ++q) acc[j][q] = 0ull;
        #pragma unroll 2
        for (int c = 0; c < D1; ++c) {
            float4 w = *(const float4*)(W2 + c * D2 + 4 * t);
            ull wp0 = pack2(w.x, w.x), wp1 = pack2(w.y, w.y);
            ull wp2 = pack2(w.z, w.z), wp3 = pack2(w.w, w.w);
            const ulonglong2* hv = (const ulonglong2*)(sm_buf + c * PP);
            #pragma unroll
            for (int q = 0; q < 5; ++q) {
                ulonglong2 h = hv[q];
                acc[0][2*q]   = ffma2(h.x, wp0, acc[0][2*q]);
                acc[0][2*q+1] = ffma2(h.y, wp0, acc[0][2*q+1]);
                acc[1][2*q]   = ffma2(h.x, wp1, acc[1][2*q]);
                acc[1][2*q+1] = ffma2(h.y, wp1, acc[1][2*q+1]);
                acc[2][2*q]   = ffma2(h.x, wp2, acc[2][2*q]);
                acc[2][2*q+1] = ffma2(h.y, wp2, acc[2][2*q+1]);
                acc[3][2*q]   = ffma2(h.x, wp3, acc[3][2*q]);
                acc[3][2*q+1] = ffma2(h.y, wp3, acc[3][2*q+1]);
            }
        }
        float4 bb = *(const float4*)(b2 + 4 * t);
        float bj[4] = {bb.x, bb.y, bb.z, bb.w};
        float mxs[4];
        #pragma unroll
        for (int j = 0; j < 4; ++j) {
            float* r = sm_hT + (4 * t + j) * PP;
            float mx = -FLT_MAX;
            #pragma unroll
            for (int q = 0; q < 10; ++q) {
                float a, b;
                unpack2(acc[j][q], a, b);
                a += bj[j]; b += bj[j];
                mx = fmaxf(mx, fmaxf(a, b));
                *(float2*)&r[2 * q] = make_float2(a, b);
            }
            mxs[j] = mx;
        }
        *(float4*)&sm_vec[4 * t] = make_float4(mxs[0], mxs[1], mxs[2], mxs[3]);
    }
    __syncthreads();

    // ---- stage 3: cat(20x512)@W3(512x256)+b3 -> BN2 -> relu -> sm_buf=h2T ----
    // cat = [h, bcast(pooled)] => h@W3[:256] + pooled@W3[256:]
    float base01x, base01y, base23x, base23y;
    {
        ull base01 = 0ull, base23 = 0ull;
        #pragma unroll 4
        for (int c = 0; c < D2; ++c) {
            const ulonglong2 wb = *(const ulonglong2*)(W3 + (size_t)(D2 + c) * D2 + 4 * t);
            float pc = sm_vec[c];
            ull pd = pack2(pc, pc);
            base01 = ffma2(wb.x, pd, base01);
            base23 = ffma2(wb.y, pd, base23);
        }
        unpack2(base01, base01x, base01y);
        unpack2(base23, base23x, base23y);
    }
    {
        ull acc[4][10];
        #pragma unroll
        for (int j = 0; j < 4; ++j)
            #pragma unroll
            for (int q = 0; q < 10; ++q) acc[j][q] = 0ull;
        #pragma unroll 2
        for (int c = 0; c < D2; ++c) {
            float4 w = *(const float4*)(W3 + c * D2 + 4 * t);
            ull wp0 = pack2(w.x, w.x), wp1 = pack2(w.y, w.y);
            ull wp2 = pack2(w.z, w.z), wp3 = pack2(w.w, w.w);
            const ulonglong2* hv = (const ulonglong2*)(sm_hT + c * PP);
            #pragma unroll
            for (int q = 0; q < 5; ++q) {
                ulonglong2 h = hv[q];
                acc[0][2*q]   = ffma2(h.x, wp0, acc[0][2*q]);
                acc[0][2*q+1] = ffma2(h.y, wp0, acc[0][2*q+1]);
                acc[1][2*q]   = ffma2(h.x, wp1, acc[1][2*q]);
                acc[1][2*q+1] = ffma2(h.y, wp1, acc[1][2*q+1]);
                acc[2][2*q]   = ffma2(h.x, wp2, acc[2][2*q]);
                acc[2][2*q+1] = ffma2(h.y, wp2, acc[2][2*q+1]);
                acc[3][2*q]   = ffma2(h.x, wp3, acc[3][2*q]);
                acc[3][2*q+1] = ffma2(h.y, wp3, acc[3][2*q+1]);
            }
        }
        float4 gg  = *(const float4*)(g2  + 4 * t);
        float4 vv  = *(const float4*)(v2  + 4 * t);
        float4 mm  = *(const float4*)(m2  + 4 * t);
        float4 ee  = *(const float4*)(be2 + 4 * t);
        float4 b3v = *(const float4*)(b3  + 4 * t);
        float sj[4], shj[4], basej[4];
        sj[0] = gg.x * rsqrtf(vv.x + 1e-5f);
        sj[1] = gg.y * rsqrtf(vv.y + 1e-5f);
        sj[2] = gg.z * rsqrtf(vv.z + 1e-5f);
        sj[3] = gg.w * rsqrtf(vv.w + 1e-5f);
        shj[0] = ee.x - mm.x * sj[0] + b3v.x * sj[0];
        shj[1] = ee.y - mm.y * sj[1] + b3v.y * sj[1];
        shj[2] = ee.z - mm.z * sj[2] + b3v.z * sj[2];
        shj[3] = ee.w - mm.w * sj[3] + b3v.w * sj[3];
        basej[0] = base01x; basej[1] = base01y; basej[2] = base23x; basej[3] = base23y;
        #pragma unroll
        for (int j = 0; j < 4; ++j) {
            float* r = sm_buf + (4 * t + j) * PP;
            #pragma unroll
            for (int q = 0; q < 10; ++q) {
                float a, b;
                unpack2(acc[j][q], a, b);
                *(float2*)&r[2 * q] =
                    make_float2(fmaxf((a + basej[j]) * sj[j] + shj[j], 0.0f),
                                fmaxf((b + basej[j]) * sj[j] + shj[j], 0.0f));
            }
        }
    }
    __syncthreads();

    // ---- stage 4: h2(20x256)@W4(256x256)+b4 -> max_p -> +type_emb -> out ----
    {
        ull acc[4][10];
        #pragma unroll
        for (int j = 0; j < 4; ++j)
            #pragma unroll
            for (int q = 0; q < 10; ++q) acc[j][q] = 0ull;
        #pragma unroll 2
        for (int c = 0; c < D2; ++c) {
            float4 w = *(const float4*)(W4 + c * D2 + 4 * t);
            ull wp0 = pack2(w.x, w.x), wp1 = pack2(w.y, w.y);
            ull wp2 = pack2(w.z, w.z), wp3 = pack2(w.w, w.w);
            const ulonglong2* hv = (const ulonglong2*)(sm_buf + c * PP);
            #pragma unroll
            for (int q = 0; q < 5; ++q) {
                ulonglong2 h = hv[q];
                acc[0][2*q]   = ffma2(h.x, wp0, acc[0][2*q]);
                acc[0][2*q+1] = ffma2(h.y, wp0, acc[0][2*q+1]);
                acc[1][2*q]   = ffma2(h.x, wp1, acc[1][2*q]);
                acc[1][2*q+1] = ffma2(h.y, wp1, acc[1][2*q+1]);
                acc[2][2*q]   = ffma2(h.x, wp2, acc[2][2*q]);
                acc[2][2*q+1] = ffma2(h.y, wp2, acc[2][2*q+1]);
                acc[3][2*q]   = ffma2(h.x, wp3, acc[3][2*q]);
                acc[3][2*q+1] = ffma2(h.y, wp3, acc[3][2*q+1]);
            }
        }
        float4 bb = *(const float4*)(b4 + 4 * t);
        float bj[4] = {bb.x, bb.y, bb.z, bb.w};
        int lb = label[idx];
        float4 tv = *(const float4*)(temb + (size_t)lb * D2 + 4 * t);
        float tj[4] = {tv.x, tv.y, tv.z, tv.w};
        float o[4];
        #pragma unroll
        for (int j = 0; j < 4; ++j) {
            float mx = -FLT_MAX;
            #pragma unroll
            for (int q = 0; q < 10; ++q) {
                float a, b;
                unpack2(acc[j][q], a, b);
                mx = fmaxf(mx, fmaxf(a, b));
            }
            o[j] = mx + bj[j] + tj[j];
        }
        *(float4*)&feats_out[(size_t)idx * D2 + 4 * t] =
            make_float4(o[0], o[1], o[2], o[3]);
    }

    // ---- sine embedding: thread t computes sine[4t..4t+3] ----
    // (sm_vec pooled is dead after stage-3 base term)
    {
        float c0 = pcr[0], c1 = pcr[1], c3 = pcr[3], c4 = pcr[4];
        float posx = (sm_pts[10 * 2]     - c0) / (c3 - c0);
        float posy = (sm_pts[10 * 2 + 1] - c1) / (c4 - c1);
        float pos = (t < 32) ? posy : posx;   // 4t < 128 <=> t < 32
        int i0 = (2 * t) & 63;                 // pair index for sine[4t],[4t+1]
        int i1 = (2 * t + 1) & 63;             // pair index for sine[4t+2],[4t+3]
        float f0 = powf(10000.0f, (float)i0 * (1.0f / 64.0f));
        float f1 = powf(10000.0f, (float)i1 * (1.0f / 64.0f));
        float a0 = pos * 6.283185307179586f / f0;
        float a1 = pos * 6.283185307179586f / f1;
        float s0, c0v, s1, c1v;
        sincosf(a0, &s0, &c0v);
        sincosf(a1, &s1, &c1v);
        *(float4*)&sm_vec[4 * t] = make_float4(s0, c0v, s1, c1v);
    }
    __syncthreads();  // fences stage-4 sm_buf reads + sine writes

    // ---- hp = relu(sine @ Wp1(256x512) + bp1): cols 4t..4t+3, 4t+256..4t+259 ----
    {
        const ulonglong2 bplo = *(const ulonglong2*)(bp1 + 4 * t);
        const ulonglong2 bphi = *(const ulonglong2*)(bp1 + 4 * t + 256);
        ull a0 = bplo.x, a1 = bplo.y, a2 = bphi.x, a3 = bphi.y;
        #pragma unroll 4
        for (int j = 0; j < 256; ++j) {
            float sv = sm_vec[j];
            ull sd = pack2(sv, sv);
            const ulonglong2 wlo = *(const ulonglong2*)(Wp1 + j * 512 + 4 * t);
            const ulonglong2 whi = *(const ulonglong2*)(Wp1 + j * 512 + 4 * t + 256);
            a0 = ffma2(wlo.x, sd, a0);
            a1 = ffma2(wlo.y, sd, a1);
            a2 = ffma2(whi.x, sd, a2);
            a3 = ffma2(whi.y, sd, a3);
        }
        float x, y;
        unpack2(a0, x, y);
        float r0 = fmaxf(x, 0.f), r1 = fmaxf(y, 0.f);
        unpack2(a1, x, y);
        float r2 = fmaxf(x, 0.f), r3 = fmaxf(y, 0.f);
        *(float4*)&sm_buf[4 * t] = make_float4(r0, r1, r2, r3);
        unpack2(a2, x, y);
        r0 = fmaxf(x, 0.f); r1 = fmaxf(y, 0.f);
        unpack2(a3, x, y);
        r2 = fmaxf(x, 0.f); r3 = fmaxf(y, 0.f);
        *(float4*)&sm_buf[4 * t + 256] = make_float4(r0, r1, r2, r3);
    }
    __syncthreads();

    // ---- pe = hp @ Wp2(512x256) + bp2 ----
    {
        const ulonglong2 bp = *(const ulonglong2*)(bp2 + 4 * t);
        ull a0 = bp.x, a1 = bp.y;
        #pragma unroll 4
        for (int k = 0; k < 512; ++k) {
            float hk = sm_buf[k];
            ull hd = pack2(hk, hk);
            const ulonglong2 w = *(const ulonglong2*)(Wp2 + k * D2 + 4 * t);
            a0 = ffma2(w.x, hd, a0);
            a1 = ffma2(w.y, hd, a1);
        }
        float x0, y0, x1, y1;
        unpack2(a0, x0, y0);
        unpack2(a1, x1, y1);
        *(float4*)&pos_out[(size_t)idx * D2 + 4 * t] = make_float4(x0, y0, x1, y1);
    }
}

extern "C" void kernel_launch(void* const* d_in, const int* in_sizes, int n_in,
                              void* d_out, int out_size) {
    (void)in_sizes; (void)n_in; (void)out_size;

    const float* tgt   = (const float*)d_in[0];
    const int*   label = (const int*)d_in[1];
    const void*  maskp = d_in[2];
    const float* W1  = (const float*)d_in[3];
    const float* b1  = (const float*)d_in[4];
    const float* g1  = (const float*)d_in[5];
    const float* be1 = (const float*)d_in[6];
    const float* m1  = (const float*)d_in[7];
    const float* v1  = (const float*)d_in[8];
    const float* W2  = (const float*)d_in[9];
    const float* b2  = (const float*)d_in[10];
    const float* W3  = (const float*)d_in[11];
    const float* b3  = (const float*)d_in[12];
    const float* g2  = (const float*)d_in[13];
    const float* be2 = (const float*)d_in[14];
    const float* m2  = (const float*)d_in[15];
    const float* v2  = (const float*)d_in[16];
    const float* W4  = (const float*)d_in[17];
    const float* b4  = (const float*)d_in[18];
    const float* temb = (const float*)d_in[19];
    const float* Wp1 = (const float*)d_in[20];
    const float* bp1 = (const float*)d_in[21];
    const float* Wp2 = (const float*)d_in[22];
    const float* bp2 = (const float*)d_in[23];
    const float* pcr = (const float*)d_in[24];

    detect_mask_kernel<<<1, 256>>>((const unsigned char*)maskp);
    map_encoder_kernel<<<BN_TOTAL, 64>>>(
        tgt, label, maskp,
        W1, b1, g1, be1, m1, v1,
        W2, b2, W3, b3, g2, be2, m2, v2,
        W4, b4, temb, Wp1, bp1, Wp2, bp2, pcr,
        (float*)d_out);
}

// round 5
// speedup vs baseline: 1.3739x; 1.3739x over previous
#include <cuda_runtime.h>
#include <float.h>

// Problem constants (fixed by the reference: B=16, N=1024, M=21, D=256, V=16)
#define BN_TOTAL (16 * 1024)
#define MPTS 21
#define PP 20      // M-1 points per polyline
#define D1 128
#define D2 256

typedef unsigned long long ull;

// ---- packed f32x2 helpers (Blackwell FFMA2) ----
__device__ __forceinline__ ull pack2(float x, float y) {
    ull r;
    asm("mov.b64 %0, {%1, %2};" : "=l"(r) : "f"(x), "f"(y));
    return r;
}
__device__ __forceinline__ void unpack2(ull v, float& x, float& y) {
    asm("mov.b64 {%0, %1}, %2;" : "=f"(x), "=f"(y) : "l"(v));
}
__device__ __forceinline__ ull ffma2(ull a, ull b, ull c) {
    ull d;
    asm("fma.rn.f32x2 %0, %1, %2, %3;" : "=l"(d) : "l"(a), "l"(b), "l"(c));
    return d;
}

__device__ int g_mask_is_byte;
__device__ float g_W23[D1 * D2];   // W2 @ W3[:256]  (128x256)
__device__ float g_bc[D2];         // b2 @ W3[:256] + b3

// Detect whether map_mask is stored as 1-byte bool or 4-byte int32.
__global__ void detect_mask_kernel(const unsigned char* __restrict__ m) {
    __shared__ int s_found;
    if (threadIdx.x == 0) s_found = 0;
    __syncthreads();
    int found = 0;
    for (int i = threadIdx.x; i < BN_TOTAL; i += blockDim.x) {
        if ((i & 3) != 0 && m[i] != 0) found = 1;
    }
    if (found) atomicOr(&s_found, 1);
    __syncthreads();
    if (threadIdx.x == 0) g_mask_is_byte = s_found;
}

// Precompute W23 = W2 @ W3[:256] and bc = b2 @ W3[:256] + b3.
// Blocks 0..31: 4 rows of W23 each. Block 32: bc (b2 treated as a row).
__global__ void precompute_w23_kernel(const float* __restrict__ W2,
                                      const float* __restrict__ W3,
                                      const float* __restrict__ b2,
                                      const float* __restrict__ b3) {
    __shared__ float rows[4][D2];
    const int blk = blockIdx.x;
    const int d = threadIdx.x;   // 0..255
    if (blk < 32) {
        #pragma unroll
        for (int r = 0; r < 4; ++r) rows[r][d] = W2[(4 * blk + r) * D2 + d];
        __syncthreads();
        float a0 = 0.f, a1 = 0.f, a2 = 0.f, a3 = 0.f;
        #pragma unroll 4
        for (int k = 0; k < D2; ++k) {
            float w = W3[k * D2 + d];
            a0 = fmaf(rows[0][k], w, a0);
            a1 = fmaf(rows[1][k], w, a1);
            a2 = fmaf(rows[2][k], w, a2);
            a3 = fmaf(rows[3][k], w, a3);
        }
        g_W23[(4 * blk + 0) * D2 + d] = a0;
        g_W23[(4 * blk + 1) * D2 + d] = a1;
        g_W23[(4 * blk + 2) * D2 + d] = a2;
        g_W23[(4 * blk + 3) * D2 + d] = a3;
    } else {
        rows[0][d] = b2[d];
        __syncthreads();
        float a = 0.f;
        #pragma unroll 4
        for (int k = 0; k < D2; ++k) a = fmaf(rows[0][k], W3[k * D2 + d], a);
        g_bc[d] = a + b3[d];
    }
}

// 128 threads/block. Thread t owns output columns (2t, 2t+1) of every GEMM
// and ALL 20 points (thread-local max-pool, h rows stream as LDS.128).
// h (stage-2 output) is never materialized: only its point-max is kept, and
// stage 3's h-contribution is re-expressed through the precomputed W23.
__global__ __launch_bounds__(128, 6) void map_encoder_kernel(
    const float* __restrict__ tgt,      // (B,N,21,2)
    const int* __restrict__ label,      // (B,N)
    const void* __restrict__ maskp,     // (B,N) bool or int32
    const float* __restrict__ W1, const float* __restrict__ b1,
    const float* __restrict__ g1, const float* __restrict__ be1,
    const float* __restrict__ m1, const float* __restrict__ v1,
    const float* __restrict__ W2, const float* __restrict__ b2,
    const float* __restrict__ W3, const float* __restrict__ b3,
    const float* __restrict__ g2, const float* __restrict__ be2,
    const float* __restrict__ m2, const float* __restrict__ v2,
    const float* __restrict__ W4, const float* __restrict__ b4,
    const float* __restrict__ temb,     // (16,256)
    const float* __restrict__ Wp1, const float* __restrict__ bp1,
    const float* __restrict__ Wp2, const float* __restrict__ bp2,
    const float* __restrict__ pcr,      // (6,)
    float* __restrict__ out)
{
    // [channel][point] transposed; 20-float (80B) rows = 5x LDS.128.
    __shared__ __align__(16) float sm_h1T[D1 * PP];  // stage1 out; later hp  (10 KB)
    __shared__ __align__(16) float sm_h2T[D2 * PP];  // stage3 out            (20 KB)
    __shared__ __align__(16) float sm_vec[D2];       // pooled -> sine
    __shared__ float sm_pts[MPTS * 2 + 2];
    __shared__ float sm_feat[PP * 6];

    const int idx = blockIdx.x;
    const int t = threadIdx.x;          // 0..127; owns cols 2t, 2t+1

    bool mask;
    if (g_mask_is_byte)
        mask = ((const unsigned char*)maskp)[idx] != 0;
    else
        mask = ((const int*)maskp)[idx] != 0;

    float* __restrict__ feats_out = out;
    float* __restrict__ pos_out   = out + (size_t)BN_TOTAL * D2;
    float* __restrict__ mask_out  = out + (size_t)2 * BN_TOTAL * D2;

    if (!mask) {
        *(float2*)&feats_out[(size_t)idx * D2 + 2 * t] = make_float2(0.0f, 0.0f);
        *(float2*)&pos_out[(size_t)idx * D2 + 2 * t]   = make_float2(0.0f, 0.0f);
        if (t == 0) mask_out[idx] = 1.0f;
        return;
    }
    if (t == 0) mask_out[idx] = 0.0f;

    // ---- load points ----
    const float* pp = tgt + (size_t)idx * MPTS * 2;
    if (t < MPTS * 2) sm_pts[t] = pp[t];
    __syncthreads();

    // ---- feature construction ----
    if (t < PP) {
        int p = t;
        float cx = sm_pts[10 * 2], cy = sm_pts[10 * 2 + 1];
        float x0 = sm_pts[2 * p],     y0 = sm_pts[2 * p + 1];
        float x1 = sm_pts[2 * p + 2], y1 = sm_pts[2 * p + 3];
        float pvx = x1 - x0, pvy = y1 - y0;
        float vn = sqrtf(pvx * pvx + pvy * pvy) + 1.0f + 1e-6f;
        float inv = 1.0f / vn;
        sm_feat[p * 6 + 0] = x0 - cx;
        sm_feat[p * 6 + 1] = y0 - cy;
        sm_feat[p * 6 + 2] = pvx;
        sm_feat[p * 6 + 3] = pvy;
        sm_feat[p * 6 + 4] = pvx * inv;
        sm_feat[p * 6 + 5] = pvy * inv;
    }
    __syncthreads();

    // ---- stage 1: feat(20x6)@W1(6x128)+b1 -> BN1 -> relu -> sm_h1T ----
    {
        int d = t;
        float w0 = W1[0 * D1 + d], w1 = W1[1 * D1 + d], w2 = W1[2 * D1 + d];
        float w3 = W1[3 * D1 + d], w4 = W1[4 * D1 + d], w5 = W1[5 * D1 + d];
        float s  = g1[d] * rsqrtf(v1[d] + 1e-5f);
        float sh = be1[d] - m1[d] * s + b1[d] * s;
        #pragma unroll
        for (int p = 0; p < PP; ++p) {
            const float* f = &sm_feat[p * 6];
            float lin = f[0] * w0 + f[1] * w1 + f[2] * w2
                      + f[3] * w3 + f[4] * w4 + f[5] * w5;
            sm_h1T[d * PP + p] = fmaxf(lin * s + sh, 0.0f);
        }
    }
    __syncthreads();

    // ---- stage 2: pooled = max_p(h1@W2 + b2), h never stored ----
    {
        ull acc0[10], acc1[10];
        #pragma unroll
        for (int q = 0; q < 10; ++q) { acc0[q] = 0ull; acc1[q] = 0ull; }
        #pragma unroll 2
        for (int c = 0; c < D1; ++c) {
            float2 w = *(const float2*)(W2 + c * D2 + 2 * t);
            ull w0 = pack2(w.x, w.x);
            ull w1 = pack2(w.y, w.y);
            const ulonglong2* hv = (const ulonglong2*)(sm_h1T + c * PP);
            #pragma unroll
            for (int q = 0; q < 5; ++q) {
                ulonglong2 h = hv[q];
                acc0[2 * q]     = ffma2(h.x, w0, acc0[2 * q]);
                acc0[2 * q + 1] = ffma2(h.y, w0, acc0[2 * q + 1]);
                acc1[2 * q]     = ffma2(h.x, w1, acc1[2 * q]);
                acc1[2 * q + 1] = ffma2(h.y, w1, acc1[2 * q + 1]);
            }
        }
        float2 bb = *(const float2*)(b2 + 2 * t);
        float mx0 = -FLT_MAX, mx1 = -FLT_MAX;
        #pragma unroll
        for (int q = 0; q < 10; ++q) {
            float a, b;
            unpack2(acc0[q], a, b);
            mx0 = fmaxf(mx0, fmaxf(a, b));
            unpack2(acc1[q], a, b);
            mx1 = fmaxf(mx1, fmaxf(a, b));
        }
        *(float2*)&sm_vec[2 * t] = make_float2(mx0 + bb.x, mx1 + bb.y);  // pooled
    }
    __syncthreads();

    // ---- stage 3: h2 = relu(BN2(h1@W23 + pooled@W3b + bc)) -> sm_h2T ----
    {
        // pooled @ W3[256:] + bc
        ull base = 0ull;
        #pragma unroll 4
        for (int c = 0; c < D2; ++c) {
            ull wb = *(const ull*)(W3 + (size_t)(D2 + c) * D2 + 2 * t);
            float pc = sm_vec[c];
            base = ffma2(wb, pack2(pc, pc), base);
        }
        float bx, by;
        unpack2(base, bx, by);
        float2 bcv = *(const float2*)(g_bc + 2 * t);
        bx += bcv.x; by += bcv.y;

        // h1 @ W23 (128 channels)
        ull acc0[10], acc1[10];
        #pragma unroll
        for (int q = 0; q < 10; ++q) { acc0[q] = 0ull; acc1[q] = 0ull; }
        #pragma unroll 2
        for (int c = 0; c < D1; ++c) {
            float2 w = *(const float2*)(g_W23 + c * D2 + 2 * t);
            ull w0 = pack2(w.x, w.x);
            ull w1 = pack2(w.y, w.y);
            const ulonglong2* hv = (const ulonglong2*)(sm_h1T + c * PP);
            #pragma unroll
            for (int q = 0; q < 5; ++q) {
                ulonglong2 h = hv[q];
                acc0[2 * q]     = ffma2(h.x, w0, acc0[2 * q]);
                acc0[2 * q + 1] = ffma2(h.y, w0, acc0[2 * q + 1]);
                acc1[2 * q]     = ffma2(h.x, w1, acc1[2 * q]);
                acc1[2 * q + 1] = ffma2(h.y, w1, acc1[2 * q + 1]);
            }
        }

        float2 gg  = *(const float2*)(g2  + 2 * t);
        float2 vv  = *(const float2*)(v2  + 2 * t);
        float2 mm  = *(const float2*)(m2  + 2 * t);
        float2 ee  = *(const float2*)(be2 + 2 * t);
        float s0 = gg.x * rsqrtf(vv.x + 1e-5f);
        float s1 = gg.y * rsqrtf(vv.y + 1e-5f);
        float sh0 = ee.x - mm.x * s0;
        float sh1 = ee.y - mm.y * s1;
        float* r0 = sm_h2T + (2 * t) * PP;
        float* r1 = sm_h2T + (2 * t + 1) * PP;
        #pragma unroll
        for (int q = 0; q < 10; ++q) {
            float a, b;
            unpack2(acc0[q], a, b);
            *(float2*)&r0[2 * q] =
                make_float2(fmaxf((a + bx) * s0 + sh0, 0.0f),
                            fmaxf((b + bx) * s0 + sh0, 0.0f));
            unpack2(acc1[q], a, b);
            *(float2*)&r1[2 * q] =
                make_float2(fmaxf((a + by) * s1 + sh1, 0.0f),
                            fmaxf((b + by) * s1 + sh1, 0.0f));
        }
    }
    __syncthreads();

    // ---- stage 4: h2(20x256)@W4(256x256)+b4 -> max_p -> +type_emb -> out ----
    {
        ull acc0[10], acc1[10];
        #pragma unroll
        for (int q = 0; q < 10; ++q) { acc0[q] = 0ull; acc1[q] = 0ull; }
        #pragma unroll 2
        for (int c = 0; c < D2; ++c) {
            float2 w = *(const float2*)(W4 + c * D2 + 2 * t);
            ull w0 = pack2(w.x, w.x);
            ull w1 = pack2(w.y, w.y);
            const ulonglong2* hv = (const ulonglong2*)(sm_h2T + c * PP);
            #pragma unroll
            for (int q = 0; q < 5; ++q) {
                ulonglong2 h = hv[q];
                acc0[2 * q]     = ffma2(h.x, w0, acc0[2 * q]);
                acc0[2 * q + 1] = ffma2(h.y, w0, acc0[2 * q + 1]);
                acc1[2 * q]     = ffma2(h.x, w1, acc1[2 * q]);
                acc1[2 * q + 1] = ffma2(h.y, w1, acc1[2 * q + 1]);
            }
        }
        float2 bb = *(const float2*)(b4 + 2 * t);
        float mx0 = -FLT_MAX, mx1 = -FLT_MAX;
        #pragma unroll
        for (int q = 0; q < 10; ++q) {
            float a, b;
            unpack2(acc0[q], a, b);
            mx0 = fmaxf(mx0, fmaxf(a, b));
            unpack2(acc1[q], a, b);
            mx1 = fmaxf(mx1, fmaxf(a, b));
        }
        int lb = label[idx];
        float2 tv = *(const float2*)(temb + (size_t)lb * D2 + 2 * t);
        *(float2*)&feats_out[(size_t)idx * D2 + 2 * t] =
            make_float2(mx0 + bb.x + tv.x, mx1 + bb.y + tv.y);
    }

    // ---- sine embedding: thread t -> sine[2t], sine[2t+1] ----
    // (sm_vec pooled dead after stage-3 base; write is fenced by stage-3 sync)
    {
        float c0 = pcr[0], c1 = pcr[1], c3 = pcr[3], c4 = pcr[4];
        float posx = (sm_pts[10 * 2]     - c0) / (c3 - c0);
        float posy = (sm_pts[10 * 2 + 1] - c1) / (c4 - c1);
        float pos = (t < 64) ? posy : posx;   // 2t < 128 <=> t < 64
        int i = t & 63;
        float freq = powf(10000.0f, (float)i * (1.0f / 64.0f));
        float arg = pos * 6.283185307179586f / freq;
        float sn, cs;
        sincosf(arg, &sn, &cs);
        *(float2*)&sm_vec[2 * t] = make_float2(sn, cs);  // even=sin, odd=cos
    }
    __syncthreads();  // fences stage-4 h2T reads + sine writes

    // ---- hp = relu(sine @ Wp1(256x512) + bp1) -> sm_h1T[0..511] ----
    {
        ull a0 = pack2(bp1[2 * t], bp1[2 * t + 1]);
        ull a1 = pack2(bp1[2 * t + 256], bp1[2 * t + 257]);
        #pragma unroll 4
        for (int j = 0; j < 256; ++j) {
            float sj = sm_vec[j];
            ull sd = pack2(sj, sj);
            a0 = ffma2(*(const ull*)(Wp1 + j * 512 + 2 * t), sd, a0);
            a1 = ffma2(*(const ull*)(Wp1 + j * 512 + 2 * t + 256), sd, a1);
        }
        float a, b;
        unpack2(a0, a, b);
        *(float2*)&sm_h1T[2 * t] = make_float2(fmaxf(a, 0.0f), fmaxf(b, 0.0f));
        unpack2(a1, a, b);
        *(float2*)&sm_h1T[2 * t + 256] = make_float2(fmaxf(a, 0.0f), fmaxf(b, 0.0f));
    }
    __syncthreads();

    // ---- pe = hp @ Wp2(512x256) + bp2 ----
    {
        ull acc = pack2(bp2[2 * t], bp2[2 * t + 1]);
        #pragma unroll 4
        for (int k = 0; k < 512; ++k) {
            float hk = sm_h1T[k];
            acc = ffma2(*(const ull*)(Wp2 + k * D2 + 2 * t), pack2(hk, hk), acc);
        }
        float a, b;
        unpack2(acc, a, b);
        *(float2*)&pos_out[(size_t)idx * D2 + 2 * t] = make_float2(a, b);
    }
}

extern "C" void kernel_launch(void* const* d_in, const int* in_sizes, int n_in,
                              void* d_out, int out_size) {
    (void)in_sizes; (void)n_in; (void)out_size;

    const float* tgt   = (const float*)d_in[0];
    const int*   label = (const int*)d_in[1];
    const void*  maskp = d_in[2];
    const float* W1  = (const float*)d_in[3];
    const float* b1  = (const float*)d_in[4];
    const float* g1  = (const float*)d_in[5];
    const float* be1 = (const float*)d_in[6];
    const float* m1  = (const float*)d_in[7];
    const float* v1  = (const float*)d_in[8];
    const float* W2  = (const float*)d_in[9];
    const float* b2  = (const float*)d_in[10];
    const float* W3  = (const float*)d_in[11];
    const float* b3  = (const float*)d_in[12];
    const float* g2  = (const float*)d_in[13];
    const float* be2 = (const float*)d_in[14];
    const float* m2  = (const float*)d_in[15];
    const float* v2  = (const float*)d_in[16];
    const float* W4  = (const float*)d_in[17];
    const float* b4  = (const float*)d_in[18];
    const float* temb = (const float*)d_in[19];
    const float* Wp1 = (const float*)d_in[20];
    const float* bp1 = (const float*)d_in[21];
    const float* Wp2 = (const float*)d_in[22];
    const float* bp2 = (const float*)d_in[23];
    const float* pcr = (const float*)d_in[24];

    detect_mask_kernel<<<1, 256>>>((const unsigned char*)maskp);
    precompute_w23_kernel<<<33, 256>>>(W2, W3, b2, b3);
    map_encoder_kernel<<<BN_TOTAL, 128>>>(
        tgt, label, maskp,
        W1, b1, g1, be1, m1, v1,
        W2, b2, W3, b3, g2, be2, m2, v2,
        W4, b4, temb, Wp1, bp1, Wp2, bp2, pcr,
        (float*)d_out);
}